// round 15
// baseline (speedup 1.0000x reference)
#include <cuda_runtime.h>
#include <cuda_bf16.h>
#include <math.h>
#include <stdint.h>

#define B_    16
#define T_    400
#define DV_   4096
#define DS_   768
#define D_    1024
#define L_    32
#define NSEG  16
#define FPS_  25
#define NPROP 136
#define HALFB 8

// ---------------- scratch (static device globals; no allocation) ----------------
__device__ float    g_Vr[B_ * T_ * D_];          // 26.2 MB
__device__ float    g_Sr[B_ * L_ * D_];          // 2.1 MB
__device__ float    g_scores[B_ * L_ * T_];
__device__ float    g_m[B_ * L_ * NSEG];
__device__ float    g_Zs[B_ * L_ * NSEG];
__device__ float    g_E[B_ * L_ * NSEG * D_];    // 33.5 MB
__device__ float    g_snorm[B_ * D_];
__device__ unsigned g_negmax[B_];

// split-bf16 W for the big GEMM (A split is fused into the GEMM)
__device__ __align__(16) __nv_bfloat16 g_Bhi[(long)D_ * DV_];       // [N,K]
__device__ __align__(16) __nv_bfloat16 g_Blo[(long)D_ * DV_];

// ---------------- helpers ----------------
__device__ __forceinline__ uint32_t smem_u32(const void* p) {
    uint32_t a;
    asm("{ .reg .u64 t; cvta.to.shared.u64 t, %1; cvt.u32.u64 %0, t; }" : "=r"(a) : "l"(p));
    return a;
}
#define CP_ASYNC16(dst, src) \
    asm volatile("cp.async.cg.shared.global [%0], [%1], 16;" :: "r"(dst), "l"(src) : "memory")
#define CP_COMMIT() asm volatile("cp.async.commit_group;" ::: "memory")
#define CP_WAIT(n)  asm volatile("cp.async.wait_group %0;" :: "n"(n) : "memory")

__device__ __forceinline__ void mma16816(float* c, const uint32_t* a, const uint32_t* b) {
    asm volatile(
        "mma.sync.aligned.m16n8k16.row.col.f32.bf16.bf16.f32 "
        "{%0,%1,%2,%3}, {%4,%5,%6,%7}, {%8,%9}, {%0,%1,%2,%3};"
        : "+f"(c[0]), "+f"(c[1]), "+f"(c[2]), "+f"(c[3])
        : "r"(a[0]), "r"(a[1]), "r"(a[2]), "r"(a[3]), "r"(b[0]), "r"(b[1]));
}

__device__ __forceinline__ void ldsm_x4(uint32_t& r0, uint32_t& r1, uint32_t& r2,
                                        uint32_t& r3, uint32_t addr) {
    asm volatile("ldmatrix.sync.aligned.m8n8.x4.shared.b16 {%0,%1,%2,%3}, [%4];"
                 : "=r"(r0), "=r"(r1), "=r"(r2), "=r"(r3) : "r"(addr));
}

// split a float2 into packed bf16x2 (hi) and packed bf16x2 (residual lo)
__device__ __forceinline__ void splitpair(float2 v, uint32_t& h, uint32_t& l) {
    __nv_bfloat162 hb = __floats2bfloat162_rn(v.x, v.y);   // .x = low half = elem k
    float2 hf = __bfloat1622float2(hb);
    __nv_bfloat162 lb = __floats2bfloat162_rn(v.x - hf.x, v.y - hf.y);
    h = *(uint32_t*)&hb;
    l = *(uint32_t*)&lb;
}

// ============================================================================
// Vr GEMM (R8-proven config, UNchanged): C = A_fp32 @ B(split bf16)^T + bias
// ============================================================================
#define BK      32
#define A_LDF   36
#define A_TB    (128 * A_LDF * 4)
#define B_LDT   40
#define B_ROWB  (B_LDT * 2)
#define B_TB    (128 * B_ROWB)
#define STAGE_B (A_TB + 2 * B_TB)
#define AH_OFF  (2 * STAGE_B)
#define AL_OFF  (AH_OFF + B_TB)
#define GEMM_SMEM (AL_OFF + B_TB)           // 98304

__device__ __forceinline__ void load_stage(
    uint32_t sbase, const float* __restrict__ Af,
    const __nv_bfloat16* __restrict__ Bh, const __nv_bfloat16* __restrict__ Bl,
    int m0, int n0, int k0, int tid)
{
#pragma unroll
    for (int i = 0; i < 4; i++) {
        int c = i * 256 + tid;
        int row = c >> 3, ch = c & 7;
        CP_ASYNC16(sbase + row * (A_LDF * 4) + ch * 16,
                   Af + (long)(m0 + row) * DV_ + k0 + ch * 4);
    }
#pragma unroll
    for (int i = 0; i < 2; i++) {
        int c = i * 256 + tid;
        int row = c >> 2, ch = c & 3;
        long roff = (long)(n0 + row) * DV_ + k0 + ch * 8;
        uint32_t dd = row * B_ROWB + ch * 16;
        CP_ASYNC16(sbase + A_TB + dd, Bh + roff);
        CP_ASYNC16(sbase + A_TB + B_TB + dd, Bl + roff);
    }
}

__global__ void __launch_bounds__(256, 2) vr_gemm(
    const float* __restrict__ Af,
    const __nv_bfloat16* __restrict__ Bh, const __nv_bfloat16* __restrict__ Bl,
    const float* __restrict__ bias, float* __restrict__ C)
{
    extern __shared__ char smc[];
    uint32_t sb = smem_u32(smc);
    int tid = threadIdx.x, wid = tid >> 5, lane = tid & 31;
    int g = lane >> 2, tig = lane & 3;
    int wm = wid >> 2, wn = wid & 3;
    int n0 = blockIdx.x * 128, m0 = blockIdx.y * 128;

    float acc[4][4][4];
#pragma unroll
    for (int a = 0; a < 4; a++)
#pragma unroll
        for (int b = 0; b < 4; b++)
#pragma unroll
            for (int cc = 0; cc < 4; cc++) acc[a][b][cc] = 0.f;

    int crow = tid >> 1, ccol = (tid & 1) * 16;
    uint32_t aRowOff = (uint32_t)(wm * 64 + (lane & 15)) * B_ROWB + (lane >> 4) * 16;
    uint32_t bRowOff = (uint32_t)(wn * 32 + (lane >> 4) * 8 + (lane & 7)) * B_ROWB
                       + ((lane >> 3) & 1) * 16;

    load_stage(sb, Af, Bh, Bl, m0, n0, 0, tid);
    CP_COMMIT();

    const int NKT = DV_ / BK;
    for (int kt = 0; kt < NKT; kt++) {
        if (kt + 1 < NKT) {
            load_stage(sb + ((kt + 1) & 1) * STAGE_B, Af, Bh, Bl,
                       m0, n0, (kt + 1) * BK, tid);
            CP_COMMIT();
            CP_WAIT(1);
        } else {
            CP_WAIT(0);
        }
        __syncthreads();

        const char* st = smc + (kt & 1) * STAGE_B;
        {
            const float* src = (const float*)st + crow * A_LDF + ccol;
            uint32_t hw[8], lw[8];
#pragma unroll
            for (int j = 0; j < 8; j++) {
                float2 v = *(const float2*)(src + 2 * j);
                splitpair(v, hw[j], lw[j]);
            }
            uint32_t* dh = (uint32_t*)(smc + AH_OFF) + crow * (B_LDT / 2) + (tid & 1) * 8;
            uint32_t* dl = (uint32_t*)(smc + AL_OFF) + crow * (B_LDT / 2) + (tid & 1) * 8;
            *(uint4*)dh       = make_uint4(hw[0], hw[1], hw[2], hw[3]);
            *(uint4*)(dh + 4) = make_uint4(hw[4], hw[5], hw[6], hw[7]);
            *(uint4*)dl       = make_uint4(lw[0], lw[1], lw[2], lw[3]);
            *(uint4*)(dl + 4) = make_uint4(lw[4], lw[5], lw[6], lw[7]);
        }
        __syncthreads();

        uint32_t aH = sb + AH_OFF + aRowOff;
        uint32_t aL = sb + AL_OFF + aRowOff;
        uint32_t bH = sb + (kt & 1) * STAGE_B + A_TB + bRowOff;
        uint32_t bL = bH + B_TB;

#pragma unroll
        for (int ks = 0; ks < 2; ks++) {
            uint32_t kso = ks * 32;
            uint32_t bh[4][2], bl[4][2];
            ldsm_x4(bh[0][0], bh[0][1], bh[1][0], bh[1][1], bH + kso);
            ldsm_x4(bh[2][0], bh[2][1], bh[3][0], bh[3][1], bH + 16 * B_ROWB + kso);
            ldsm_x4(bl[0][0], bl[0][1], bl[1][0], bl[1][1], bL + kso);
            ldsm_x4(bl[2][0], bl[2][1], bl[3][0], bl[3][1], bL + 16 * B_ROWB + kso);
#pragma unroll
            for (int mi = 0; mi < 4; mi++) {
                uint32_t ah[4], al[4];
                ldsm_x4(ah[0], ah[1], ah[2], ah[3], aH + mi * 16 * B_ROWB + kso);
                ldsm_x4(al[0], al[1], al[2], al[3], aL + mi * 16 * B_ROWB + kso);
#pragma unroll
                for (int ni = 0; ni < 4; ni++) mma16816(acc[mi][ni], ah, bh[ni]);
#pragma unroll
                for (int ni = 0; ni < 4; ni++) mma16816(acc[mi][ni], ah, bl[ni]);
#pragma unroll
                for (int ni = 0; ni < 4; ni++) mma16816(acc[mi][ni], al, bh[ni]);
            }
        }
        __syncthreads();
    }

#pragma unroll
    for (int mi = 0; mi < 4; mi++) {
        int mA = m0 + wm * 64 + mi * 16 + g;
#pragma unroll
        for (int ni = 0; ni < 4; ni++) {
            int n = n0 + wn * 32 + ni * 8 + tig * 2;
            float b0 = bias[n], b1 = bias[n + 1];
            float2 v0 = make_float2(acc[mi][ni][0] + b0, acc[mi][ni][1] + b1);
            float2 v1 = make_float2(acc[mi][ni][2] + b0, acc[mi][ni][3] + b1);
            *(float2*)&C[(long)mA * D_ + n] = v0;
            *(float2*)&C[(long)(mA + 8) * D_ + n] = v1;
        }
    }
}

// W [K=4096, N=1024] fp32 -> transposed split bf16 [N, K]
__global__ void splitW_kernel(const float* __restrict__ W,
                              __nv_bfloat16* __restrict__ hi, __nv_bfloat16* __restrict__ lo)
{
    __shared__ float t[32][33];
    int k0 = blockIdx.x * 32, n0 = blockIdx.y * 32;
    int tx = threadIdx.x, ty = threadIdx.y;
#pragma unroll
    for (int i = 0; i < 32; i += 8)
        t[ty + i][tx] = W[(long)(k0 + ty + i) * D_ + n0 + tx];
    __syncthreads();
#pragma unroll
    for (int i = 0; i < 32; i += 8) {
        int n = n0 + ty + i, k = k0 + tx;
        float x = t[tx][ty + i];
        __nv_bfloat16 h = __float2bfloat16(x);
        hi[(long)n * DV_ + k] = h;
        lo[(long)n * DV_ + k] = __float2bfloat16(x - __bfloat162float(h));
    }
}

// ---------------- Sr GEMM 64x64 + fused column-norm epilogue ----------------
// tile rows = 2 complete batches (2 x 32 l) -> snorm computed in-block.
__global__ void sgemm64_bias_snorm(const float* __restrict__ A, const float* __restrict__ Bm,
                                   const float* __restrict__ bias, float* __restrict__ C,
                                   float* __restrict__ snorm, int M, int N, int K)
{
    const int BKs = 16;
    __shared__ float As[BKs][68];
    __shared__ float Bs[BKs][68];
    __shared__ float rbuf[16][68];

    int tid = threadIdx.x;
    int m0 = blockIdx.y * 64, n0 = blockIdx.x * 64;
    int ty = tid >> 4, tx = tid & 15;

    float acc[4][4];
#pragma unroll
    for (int i = 0; i < 4; i++)
#pragma unroll
        for (int j = 0; j < 4; j++) acc[i][j] = 0.f;

    int arow = tid >> 2, acol = (tid & 3) * 4;
    int brow = tid >> 4, bcol = (tid & 15) * 4;

    float4 ra = *(const float4*)&A[(long)(m0 + arow) * K + acol];
    float4 rb = *(const float4*)&Bm[(long)brow * N + n0 + bcol];

    for (int k0 = 0; k0 < K; k0 += BKs) {
        As[acol + 0][arow] = ra.x; As[acol + 1][arow] = ra.y;
        As[acol + 2][arow] = ra.z; As[acol + 3][arow] = ra.w;
        Bs[brow][bcol + 0] = rb.x; Bs[brow][bcol + 1] = rb.y;
        Bs[brow][bcol + 2] = rb.z; Bs[brow][bcol + 3] = rb.w;
        __syncthreads();

        if (k0 + BKs < K) {
            ra = *(const float4*)&A[(long)(m0 + arow) * K + k0 + BKs + acol];
            rb = *(const float4*)&Bm[(long)(k0 + BKs + brow) * N + n0 + bcol];
        }
#pragma unroll
        for (int kk = 0; kk < BKs; kk++) {
            float4 a = *(const float4*)&As[kk][ty * 4];
            float4 b = *(const float4*)&Bs[kk][tx * 4];
            float av[4] = {a.x, a.y, a.z, a.w};
            float bv[4] = {b.x, b.y, b.z, b.w};
#pragma unroll
            for (int i = 0; i < 4; i++)
#pragma unroll
                for (int j = 0; j < 4; j++) acc[i][j] += av[i] * bv[j];
        }
        __syncthreads();
    }

    float4 bb = *(const float4*)&bias[n0 + tx * 4];
    float bvv[4] = {bb.x, bb.y, bb.z, bb.w};
    float csum[4] = {0.f, 0.f, 0.f, 0.f};
#pragma unroll
    for (int i = 0; i < 4; i++) {
        float4 o;
        o.x = acc[i][0] + bvv[0]; o.y = acc[i][1] + bvv[1];
        o.z = acc[i][2] + bvv[2]; o.w = acc[i][3] + bvv[3];
        *(float4*)&C[(long)(m0 + ty * 4 + i) * N + n0 + tx * 4] = o;
        csum[0] += o.x * o.x; csum[1] += o.y * o.y;
        csum[2] += o.z * o.z; csum[3] += o.w * o.w;
    }
    // reduce over 8 ty values per batch (ty<8 -> batch 0 of tile, ty>=8 -> batch 1)
#pragma unroll
    for (int j = 0; j < 4; j++) rbuf[ty][tx * 4 + j] = csum[j];
    __syncthreads();
    if (ty < 2) {
        int b = m0 / L_ + ty;               // global batch index
#pragma unroll
        for (int j = 0; j < 4; j++) {
            int col = tx * 4 + j;
            float s = 0.f;
#pragma unroll
            for (int k = 0; k < 8; k++) s += rbuf[ty * 8 + k][col];
            snorm[b * D_ + n0 + col] = sqrtf(s);
        }
    }
}

// ---------------- scores[b,l,t] (batch-offset) ----------------
__global__ void scores_kernel(int bbase)
{
    int b = bbase + blockIdx.y;
    int t0 = blockIdx.x * 64;
    __shared__ float sS[32][36];
    __shared__ float sV[32][68];
    int tid = threadIdx.x;
    int ty = tid >> 4, tx = tid & 15;
    float acc[2][4] = {{0, 0, 0, 0}, {0, 0, 0, 0}};

    int lrow = tid >> 3, kc = (tid & 7) * 4;
    for (int k0 = 0; k0 < D_; k0 += 32) {
        {
            float4 v = *(const float4*)&g_Sr[(b * L_ + lrow) * D_ + k0 + kc];
            sS[kc + 0][lrow] = v.x; sS[kc + 1][lrow] = v.y;
            sS[kc + 2][lrow] = v.z; sS[kc + 3][lrow] = v.w;
        }
#pragma unroll
        for (int i = 0; i < 2; i++) {
            int tt = lrow + i * 32;
            int t = t0 + tt;
            float4 w = make_float4(0.f, 0.f, 0.f, 0.f);
            if (t < T_) w = *(const float4*)&g_Vr[((long)b * T_ + t) * D_ + k0 + kc];
            sV[kc + 0][tt] = w.x; sV[kc + 1][tt] = w.y;
            sV[kc + 2][tt] = w.z; sV[kc + 3][tt] = w.w;
        }
        __syncthreads();
#pragma unroll
        for (int kk = 0; kk < 32; kk++) {
            float a0 = sS[kk][ty * 2], a1 = sS[kk][ty * 2 + 1];
            float4 bv = *(const float4*)&sV[kk][tx * 4];
            acc[0][0] += a0 * bv.x; acc[0][1] += a0 * bv.y;
            acc[0][2] += a0 * bv.z; acc[0][3] += a0 * bv.w;
            acc[1][0] += a1 * bv.x; acc[1][1] += a1 * bv.y;
            acc[1][2] += a1 * bv.z; acc[1][3] += a1 * bv.w;
        }
        __syncthreads();
    }
#pragma unroll
    for (int i = 0; i < 2; i++) {
        int l = ty * 2 + i;
#pragma unroll
        for (int j = 0; j < 4; j++) {
            int t = t0 + tx * 4 + j;
            if (t < T_) g_scores[(b * L_ + l) * T_ + t] = acc[i][j];
        }
    }
}

// ---------------- fused segprep + E aggregation (batch-offset) ----------------
// block (dc, g, b): computes m/Z/ws for segment g in-block, then E.
__global__ void eagg_kernel(int bbase)
{
    int dc = blockIdx.x, g = blockIdx.y, b = bbase + blockIdx.z;
    int tid = threadIdx.x;
    int d = dc * 256 + tid;
    __shared__ float Vs[FPS_][256];
    __shared__ float sl[L_][FPS_ + 1];   // raw scores then reused
    __shared__ float ws[L_][FPS_ + 1];
    __shared__ float sm[L_];

#pragma unroll
    for (int t = 0; t < FPS_; t++)
        Vs[t][tid] = g_Vr[((long)b * T_ + g * FPS_ + t) * D_ + d];
    for (int i = tid; i < L_ * FPS_; i += 256) {
        int l = i / FPS_, t = i % FPS_;
        sl[l][t] = g_scores[(b * L_ + l) * T_ + g * FPS_ + t];
    }
    __syncthreads();

    if (tid < L_) {   // one thread per l: identical order to original segprep
        int l = tid;
        float mx = -INFINITY;
#pragma unroll
        for (int i = 0; i < FPS_; i++) mx = fmaxf(mx, sl[l][i]);
        float z = 0.f;
#pragma unroll
        for (int i = 0; i < FPS_; i++) z += expf(sl[l][i] - mx);
        sm[l] = mx;
        if (dc == 0) {
            g_m[(b * L_ + l) * NSEG + g] = mx;
            g_Zs[(b * L_ + l) * NSEG + g] = z;
        }
    }
    __syncthreads();
    for (int i = tid; i < L_ * FPS_; i += 256) {
        int l = i / FPS_, t = i % FPS_;
        ws[l][t] = expf(sl[l][t] - sm[l]);
    }
    __syncthreads();

    for (int l = 0; l < L_; l++) {
        float acc = 0.f;
#pragma unroll
        for (int t = 0; t < FPS_; t++) acc += ws[l][t] * Vs[t][tid];
        g_E[((long)(b * L_ + l) * NSEG + g) * D_ + d] = acc;
    }
}

// ============================================================================
// prop_kernel v3: barrier-free chain streaming (batch-offset). UNchanged.
// ============================================================================
#define PCH 128
__global__ void __launch_bounds__(PCH) prop_kernel(const int* __restrict__ ytrue,
                                                   float* __restrict__ outPos, int bbase)
{
    int b = bbase + blockIdx.y, dc = blockIdx.x, sg = blockIdx.z;
    int tid = threadIdx.x;
    int d = dc * PCH + tid;

    __shared__ float s_m[L_][NSEG], s_Z[L_][NSEG];
    __shared__ float sSr[L_][PCH];
    __shared__ float c_sc[40][L_], c_an[40][L_], c_iz[40][L_];

    for (int i = tid; i < L_ * NSEG; i += PCH) {
        int l = i >> 4, g = i & 15;
        s_m[l][g] = g_m[(b * L_ + l) * NSEG + g];
        s_Z[l][g] = g_Zs[(b * L_ + l) * NSEG + g];
    }
    for (int i = tid; i < L_ * PCH; i += PCH) {
        int l = i / PCH, j = i % PCH;
        sSr[l][j] = g_Sr[(b * L_ + l) * D_ + dc * PCH + j];
    }
    __syncthreads();

    {
        int l = tid & 31, ci = tid >> 5;
        int s = sg + 4 * ci;
        int base = 0;
#pragma unroll
        for (int j = 0; j < 4; j++) if (j < ci) base += NSEG - (sg + 4 * j);
        float M = s_m[l][s], Zw = s_Z[l][s];
        c_sc[base][l] = 0.f; c_an[base][l] = 1.f; c_iz[base][l] = 1.f / Zw;
        for (int e = s + 1; e < NSEG; e++) {
            float mv = s_m[l][e];
            float Mn = fmaxf(M, mv);
            float sc = expf(M - Mn), an = expf(mv - Mn);
            Zw = Zw * sc + an * s_Z[l][e];
            M = Mn;
            int st = base + e - s;
            c_sc[st][l] = sc; c_an[st][l] = an; c_iz[st][l] = 1.f / Zw;
        }
    }
    __syncthreads();

    float sn = g_snorm[b * D_ + d];
    int ys = ytrue[2 * b], ye = ytrue[2 * b + 1];
    float negmax = -INFINITY;

    int base = 0;
#pragma unroll 1
    for (int ci = 0; ci < 4; ci++) {
        int s = sg + 4 * ci;
        float U[L_];
#pragma unroll
        for (int l = 0; l < L_; l++) U[l] = 0.f;
#pragma unroll 1
        for (int e = s; e < NSEG; e++) {
            int st = base + e - s;
            float num = 0.f, sq = 0.f;
            const float* Eb = g_E + ((long)(b * L_) * NSEG + e) * D_ + d;
#pragma unroll
            for (int l = 0; l < L_; l++) {
                float Ev = Eb[(long)l * NSEG * D_];
                float u = U[l] * c_sc[st][l] + c_an[st][l] * Ev;
                U[l] = u;
                float o = u * c_iz[st][l];
                num += o * sSr[l][tid];
                sq += o * o;
            }
            float scv = num / (sqrtf(sq) * sn + 1e-15f);
            if (s == ys && e == ye) outPos[b * D_ + d] = scv;
            else negmax = fmaxf(negmax, scv);
        }
        base += NSEG - s;
    }

#pragma unroll
    for (int off = 16; off; off >>= 1)
        negmax = fmaxf(negmax, __shfl_xor_sync(0xffffffffu, negmax, off));
    __shared__ float wm[4];
    if ((tid & 31) == 0) wm[tid >> 5] = negmax;
    __syncthreads();
    if (tid == 0) {
        float v = fmaxf(fmaxf(wm[0], wm[1]), fmaxf(wm[2], wm[3]));
        unsigned u = __float_as_uint(v);
        u = (u & 0x80000000u) ? ~u : (u | 0x80000000u);
        atomicMax(&g_negmax[b], u);
    }
}

__global__ void init_neg()
{
    if (threadIdx.x < B_) g_negmax[threadIdx.x] = 0x007FFFFFu;
}

__global__ void fin_kernel(float* __restrict__ outNeg)
{
    int b = threadIdx.x;
    if (b < B_) {
        unsigned u = g_negmax[b];
        unsigned bits = (u & 0x80000000u) ? (u ^ 0x80000000u) : ~u;
        outNeg[b] = __uint_as_float(bits);
    }
}

// ---------------- launch ----------------
extern "C" void kernel_launch(void* const* d_in, const int* in_sizes, int n_in,
                              void* d_out, int out_size)
{
    const float* videos    = (const float*)d_in[0];
    const float* sentences = (const float*)d_in[1];
    const float* Wv        = (const float*)d_in[2];
    const float* bv        = (const float*)d_in[3];
    const float* Ws        = (const float*)d_in[4];
    const float* bs        = (const float*)d_in[5];
    const int*   ytrue     = (const int*)d_in[6];
    float* out = (float*)d_out;

    float *pVr = nullptr, *pSr = nullptr, *pSn = nullptr;
    void *pBhi = nullptr, *pBlo = nullptr;
    cudaGetSymbolAddress((void**)&pVr, g_Vr);
    cudaGetSymbolAddress((void**)&pSr, g_Sr);
    cudaGetSymbolAddress((void**)&pSn, g_snorm);
    cudaGetSymbolAddress(&pBhi, g_Bhi);
    cudaGetSymbolAddress(&pBlo, g_Blo);

    cudaFuncSetAttribute(vr_gemm, cudaFuncAttributeMaxDynamicSharedMemorySize, GEMM_SMEM);

    static cudaStream_t s2 = nullptr, s3 = nullptr;
    static cudaEvent_t evFork = nullptr, evSr = nullptr, evA = nullptr, evH1 = nullptr;
    if (s2 == nullptr) {
        cudaStreamCreateWithFlags(&s2, cudaStreamNonBlocking);
        cudaStreamCreateWithFlags(&s3, cudaStreamNonBlocking);
        cudaEventCreateWithFlags(&evFork, cudaEventDisableTiming);
        cudaEventCreateWithFlags(&evSr, cudaEventDisableTiming);
        cudaEventCreateWithFlags(&evA, cudaEventDisableTiming);
        cudaEventCreateWithFlags(&evH1, cudaEventDisableTiming);
    }

    init_neg<<<1, 32>>>();

    // fork: Sr path (sgemm64 with fused snorm) on s2
    cudaEventRecord(evFork, 0);
    cudaStreamWaitEvent(s2, evFork, 0);
    sgemm64_bias_snorm<<<dim3(D_ / 64, (B_ * L_) / 64), 256, 0, s2>>>(
        sentences, Ws, bs, pSr, pSn, B_ * L_, D_, DS_);
    cudaEventRecord(evSr, s2);

    // Vr path on the main stream: splitW, single full GEMM
    splitW_kernel<<<dim3(DV_ / 32, D_ / 32), dim3(32, 8)>>>(Wv,
        (__nv_bfloat16*)pBhi, (__nv_bfloat16*)pBlo);
    vr_gemm<<<dim3(D_ / 128, (B_ * T_) / 128), 256, GEMM_SMEM>>>(
        videos, (const __nv_bfloat16*)pBhi, (const __nv_bfloat16*)pBlo, bv, pVr);
    cudaEventRecord(evA, 0);

    // s3: batches 0..7 chain
    cudaStreamWaitEvent(s3, evA, 0);
    cudaStreamWaitEvent(s3, evSr, 0);
    scores_kernel<<<dim3((T_ + 63) / 64, HALFB), 256, 0, s3>>>(0);
    eagg_kernel<<<dim3(D_ / 256, NSEG, HALFB), 256, 0, s3>>>(0);
    prop_kernel<<<dim3(D_ / PCH, HALFB, 4), PCH, 0, s3>>>(ytrue, out, 0);
    cudaEventRecord(evH1, s3);

    // main: batches 8..15 chain
    cudaStreamWaitEvent(0, evSr, 0);
    scores_kernel<<<dim3((T_ + 63) / 64, HALFB), 256>>>(HALFB);
    eagg_kernel<<<dim3(D_ / 256, NSEG, HALFB), 256>>>(HALFB);
    prop_kernel<<<dim3(D_ / PCH, HALFB, 4), PCH>>>(ytrue, out, HALFB);

    cudaStreamWaitEvent(0, evH1, 0);
    fin_kernel<<<1, 32>>>(out + B_ * D_);
}

// round 16
// speedup vs baseline: 1.7357x; 1.7357x over previous
#include <cuda_runtime.h>
#include <cuda_bf16.h>
#include <math.h>
#include <stdint.h>

#define B_    16
#define T_    400
#define DV_   4096
#define DS_   768
#define D_    1024
#define L_    32
#define NSEG  16
#define FPS_  25
#define NPROP 136
#define HALFB 8

// ---------------- scratch (static device globals; no allocation) ----------------
__device__ float    g_Vr[B_ * T_ * D_];          // 26.2 MB
__device__ float    g_Sr[B_ * L_ * D_];          // 2.1 MB
__device__ float    g_scores[B_ * L_ * T_];
__device__ float    g_m[B_ * L_ * NSEG];
__device__ float    g_Zs[B_ * L_ * NSEG];
__device__ float    g_E[B_ * L_ * NSEG * D_];    // 33.5 MB
__device__ float    g_snorm[B_ * D_];
__device__ unsigned g_negmax[B_];

// split-bf16 W for the big GEMM (A split is fused into the GEMM)
__device__ __align__(16) __nv_bfloat16 g_Bhi[(long)D_ * DV_];       // [N,K]
__device__ __align__(16) __nv_bfloat16 g_Blo[(long)D_ * DV_];

// ---------------- helpers ----------------
__device__ __forceinline__ uint32_t smem_u32(const void* p) {
    uint32_t a;
    asm("{ .reg .u64 t; cvta.to.shared.u64 t, %1; cvt.u32.u64 %0, t; }" : "=r"(a) : "l"(p));
    return a;
}
#define CP_ASYNC16(dst, src) \
    asm volatile("cp.async.cg.shared.global [%0], [%1], 16;" :: "r"(dst), "l"(src) : "memory")
#define CP_COMMIT() asm volatile("cp.async.commit_group;" ::: "memory")
#define CP_WAIT(n)  asm volatile("cp.async.wait_group %0;" :: "n"(n) : "memory")

__device__ __forceinline__ void mma16816(float* c, const uint32_t* a, const uint32_t* b) {
    asm volatile(
        "mma.sync.aligned.m16n8k16.row.col.f32.bf16.bf16.f32 "
        "{%0,%1,%2,%3}, {%4,%5,%6,%7}, {%8,%9}, {%0,%1,%2,%3};"
        : "+f"(c[0]), "+f"(c[1]), "+f"(c[2]), "+f"(c[3])
        : "r"(a[0]), "r"(a[1]), "r"(a[2]), "r"(a[3]), "r"(b[0]), "r"(b[1]));
}

__device__ __forceinline__ void ldsm_x4(uint32_t& r0, uint32_t& r1, uint32_t& r2,
                                        uint32_t& r3, uint32_t addr) {
    asm volatile("ldmatrix.sync.aligned.m8n8.x4.shared.b16 {%0,%1,%2,%3}, [%4];"
                 : "=r"(r0), "=r"(r1), "=r"(r2), "=r"(r3) : "r"(addr));
}

// split a float2 into packed bf16x2 (hi) and packed bf16x2 (residual lo)
__device__ __forceinline__ void splitpair(float2 v, uint32_t& h, uint32_t& l) {
    __nv_bfloat162 hb = __floats2bfloat162_rn(v.x, v.y);   // .x = low half = elem k
    float2 hf = __bfloat1622float2(hb);
    __nv_bfloat162 lb = __floats2bfloat162_rn(v.x - hf.x, v.y - hf.y);
    h = *(uint32_t*)&hb;
    l = *(uint32_t*)&lb;
}

// ============================================================================
// Vr GEMM (R8-proven config, UNchanged): C = A_fp32 @ B(split bf16)^T + bias
// ============================================================================
#define BK      32
#define A_LDF   36
#define A_TB    (128 * A_LDF * 4)
#define B_LDT   40
#define B_ROWB  (B_LDT * 2)
#define B_TB    (128 * B_ROWB)
#define STAGE_B (A_TB + 2 * B_TB)
#define AH_OFF  (2 * STAGE_B)
#define AL_OFF  (AH_OFF + B_TB)
#define GEMM_SMEM (AL_OFF + B_TB)           // 98304

__device__ __forceinline__ void load_stage(
    uint32_t sbase, const float* __restrict__ Af,
    const __nv_bfloat16* __restrict__ Bh, const __nv_bfloat16* __restrict__ Bl,
    int m0, int n0, int k0, int tid)
{
#pragma unroll
    for (int i = 0; i < 4; i++) {
        int c = i * 256 + tid;
        int row = c >> 3, ch = c & 7;
        CP_ASYNC16(sbase + row * (A_LDF * 4) + ch * 16,
                   Af + (long)(m0 + row) * DV_ + k0 + ch * 4);
    }
#pragma unroll
    for (int i = 0; i < 2; i++) {
        int c = i * 256 + tid;
        int row = c >> 2, ch = c & 3;
        long roff = (long)(n0 + row) * DV_ + k0 + ch * 8;
        uint32_t dd = row * B_ROWB + ch * 16;
        CP_ASYNC16(sbase + A_TB + dd, Bh + roff);
        CP_ASYNC16(sbase + A_TB + B_TB + dd, Bl + roff);
    }
}

__global__ void __launch_bounds__(256, 2) vr_gemm(
    const float* __restrict__ Af,
    const __nv_bfloat16* __restrict__ Bh, const __nv_bfloat16* __restrict__ Bl,
    const float* __restrict__ bias, float* __restrict__ C)
{
    extern __shared__ char smc[];
    uint32_t sb = smem_u32(smc);
    int tid = threadIdx.x, wid = tid >> 5, lane = tid & 31;
    int g = lane >> 2, tig = lane & 3;
    int wm = wid >> 2, wn = wid & 3;
    int n0 = blockIdx.x * 128, m0 = blockIdx.y * 128;

    float acc[4][4][4];
#pragma unroll
    for (int a = 0; a < 4; a++)
#pragma unroll
        for (int b = 0; b < 4; b++)
#pragma unroll
            for (int cc = 0; cc < 4; cc++) acc[a][b][cc] = 0.f;

    int crow = tid >> 1, ccol = (tid & 1) * 16;
    uint32_t aRowOff = (uint32_t)(wm * 64 + (lane & 15)) * B_ROWB + (lane >> 4) * 16;
    uint32_t bRowOff = (uint32_t)(wn * 32 + (lane >> 4) * 8 + (lane & 7)) * B_ROWB
                       + ((lane >> 3) & 1) * 16;

    load_stage(sb, Af, Bh, Bl, m0, n0, 0, tid);
    CP_COMMIT();

    const int NKT = DV_ / BK;
    for (int kt = 0; kt < NKT; kt++) {
        if (kt + 1 < NKT) {
            load_stage(sb + ((kt + 1) & 1) * STAGE_B, Af, Bh, Bl,
                       m0, n0, (kt + 1) * BK, tid);
            CP_COMMIT();
            CP_WAIT(1);
        } else {
            CP_WAIT(0);
        }
        __syncthreads();

        const char* st = smc + (kt & 1) * STAGE_B;
        {
            const float* src = (const float*)st + crow * A_LDF + ccol;
            uint32_t hw[8], lw[8];
#pragma unroll
            for (int j = 0; j < 8; j++) {
                float2 v = *(const float2*)(src + 2 * j);
                splitpair(v, hw[j], lw[j]);
            }
            uint32_t* dh = (uint32_t*)(smc + AH_OFF) + crow * (B_LDT / 2) + (tid & 1) * 8;
            uint32_t* dl = (uint32_t*)(smc + AL_OFF) + crow * (B_LDT / 2) + (tid & 1) * 8;
            *(uint4*)dh       = make_uint4(hw[0], hw[1], hw[2], hw[3]);
            *(uint4*)(dh + 4) = make_uint4(hw[4], hw[5], hw[6], hw[7]);
            *(uint4*)dl       = make_uint4(lw[0], lw[1], lw[2], lw[3]);
            *(uint4*)(dl + 4) = make_uint4(lw[4], lw[5], lw[6], lw[7]);
        }
        __syncthreads();

        uint32_t aH = sb + AH_OFF + aRowOff;
        uint32_t aL = sb + AL_OFF + aRowOff;
        uint32_t bH = sb + (kt & 1) * STAGE_B + A_TB + bRowOff;
        uint32_t bL = bH + B_TB;

#pragma unroll
        for (int ks = 0; ks < 2; ks++) {
            uint32_t kso = ks * 32;
            uint32_t bh[4][2], bl[4][2];
            ldsm_x4(bh[0][0], bh[0][1], bh[1][0], bh[1][1], bH + kso);
            ldsm_x4(bh[2][0], bh[2][1], bh[3][0], bh[3][1], bH + 16 * B_ROWB + kso);
            ldsm_x4(bl[0][0], bl[0][1], bl[1][0], bl[1][1], bL + kso);
            ldsm_x4(bl[2][0], bl[2][1], bl[3][0], bl[3][1], bL + 16 * B_ROWB + kso);
#pragma unroll
            for (int mi = 0; mi < 4; mi++) {
                uint32_t ah[4], al[4];
                ldsm_x4(ah[0], ah[1], ah[2], ah[3], aH + mi * 16 * B_ROWB + kso);
                ldsm_x4(al[0], al[1], al[2], al[3], aL + mi * 16 * B_ROWB + kso);
#pragma unroll
                for (int ni = 0; ni < 4; ni++) mma16816(acc[mi][ni], ah, bh[ni]);
#pragma unroll
                for (int ni = 0; ni < 4; ni++) mma16816(acc[mi][ni], ah, bl[ni]);
#pragma unroll
                for (int ni = 0; ni < 4; ni++) mma16816(acc[mi][ni], al, bh[ni]);
            }
        }
        __syncthreads();
    }

#pragma unroll
    for (int mi = 0; mi < 4; mi++) {
        int mA = m0 + wm * 64 + mi * 16 + g;
#pragma unroll
        for (int ni = 0; ni < 4; ni++) {
            int n = n0 + wn * 32 + ni * 8 + tig * 2;
            float b0 = bias[n], b1 = bias[n + 1];
            float2 v0 = make_float2(acc[mi][ni][0] + b0, acc[mi][ni][1] + b1);
            float2 v1 = make_float2(acc[mi][ni][2] + b0, acc[mi][ni][3] + b1);
            *(float2*)&C[(long)mA * D_ + n] = v0;
            *(float2*)&C[(long)(mA + 8) * D_ + n] = v1;
        }
    }
}

// W [K=4096, N=1024] fp32 -> transposed split bf16 [N, K]
__global__ void splitW_kernel(const float* __restrict__ W,
                              __nv_bfloat16* __restrict__ hi, __nv_bfloat16* __restrict__ lo)
{
    __shared__ float t[32][33];
    int k0 = blockIdx.x * 32, n0 = blockIdx.y * 32;
    int tx = threadIdx.x, ty = threadIdx.y;
#pragma unroll
    for (int i = 0; i < 32; i += 8)
        t[ty + i][tx] = W[(long)(k0 + ty + i) * D_ + n0 + tx];
    __syncthreads();
#pragma unroll
    for (int i = 0; i < 32; i += 8) {
        int n = n0 + ty + i, k = k0 + tx;
        float x = t[tx][ty + i];
        __nv_bfloat16 h = __float2bfloat16(x);
        hi[(long)n * DV_ + k] = h;
        lo[(long)n * DV_ + k] = __float2bfloat16(x - __bfloat162float(h));
    }
}

// ---------------- fp32 SGEMM 64x64 tiles (Sr), register-pipelined (R14) -------
__global__ void sgemm64_bias(const float* __restrict__ A, const float* __restrict__ Bm,
                             const float* __restrict__ bias, float* __restrict__ C,
                             int M, int N, int K)
{
    const int BKs = 16;
    __shared__ float As[BKs][68];
    __shared__ float Bs[BKs][68];

    int tid = threadIdx.x;
    int m0 = blockIdx.y * 64, n0 = blockIdx.x * 64;
    int ty = tid >> 4, tx = tid & 15;

    float acc[4][4];
#pragma unroll
    for (int i = 0; i < 4; i++)
#pragma unroll
        for (int j = 0; j < 4; j++) acc[i][j] = 0.f;

    int arow = tid >> 2, acol = (tid & 3) * 4;
    int brow = tid >> 4, bcol = (tid & 15) * 4;

    float4 ra = *(const float4*)&A[(long)(m0 + arow) * K + acol];
    float4 rb = *(const float4*)&Bm[(long)brow * N + n0 + bcol];

    for (int k0 = 0; k0 < K; k0 += BKs) {
        As[acol + 0][arow] = ra.x; As[acol + 1][arow] = ra.y;
        As[acol + 2][arow] = ra.z; As[acol + 3][arow] = ra.w;
        Bs[brow][bcol + 0] = rb.x; Bs[brow][bcol + 1] = rb.y;
        Bs[brow][bcol + 2] = rb.z; Bs[brow][bcol + 3] = rb.w;
        __syncthreads();

        if (k0 + BKs < K) {
            ra = *(const float4*)&A[(long)(m0 + arow) * K + k0 + BKs + acol];
            rb = *(const float4*)&Bm[(long)(k0 + BKs + brow) * N + n0 + bcol];
        }
#pragma unroll
        for (int kk = 0; kk < BKs; kk++) {
            float4 a = *(const float4*)&As[kk][ty * 4];
            float4 b = *(const float4*)&Bs[kk][tx * 4];
            float av[4] = {a.x, a.y, a.z, a.w};
            float bv[4] = {b.x, b.y, b.z, b.w};
#pragma unroll
            for (int i = 0; i < 4; i++)
#pragma unroll
                for (int j = 0; j < 4; j++) acc[i][j] += av[i] * bv[j];
        }
        __syncthreads();
    }

    float4 bb = *(const float4*)&bias[n0 + tx * 4];
    float bvv[4] = {bb.x, bb.y, bb.z, bb.w};
#pragma unroll
    for (int i = 0; i < 4; i++) {
        float4 o;
        o.x = acc[i][0] + bvv[0]; o.y = acc[i][1] + bvv[1];
        o.z = acc[i][2] + bvv[2]; o.w = acc[i][3] + bvv[3];
        *(float4*)&C[(long)(m0 + ty * 4 + i) * N + n0 + tx * 4] = o;
    }
}

// ---------------- Sr column norms (R14 original) ----------------
__global__ void snorm_kernel()
{
    int id = blockIdx.x * 256 + threadIdx.x;
    int b = id >> 10, d = id & 1023;
    float s = 0.f;
#pragma unroll
    for (int l = 0; l < L_; l++) {
        float v = g_Sr[(b * L_ + l) * D_ + d];
        s += v * v;
    }
    g_snorm[id] = sqrtf(s);
}

// ---------------- scores[b,l,t] (batch-offset) ----------------
__global__ void scores_kernel(int bbase)
{
    int b = bbase + blockIdx.y;
    int t0 = blockIdx.x * 64;
    __shared__ float sS[32][36];
    __shared__ float sV[32][68];
    int tid = threadIdx.x;
    int ty = tid >> 4, tx = tid & 15;
    float acc[2][4] = {{0, 0, 0, 0}, {0, 0, 0, 0}};

    int lrow = tid >> 3, kc = (tid & 7) * 4;
    for (int k0 = 0; k0 < D_; k0 += 32) {
        {
            float4 v = *(const float4*)&g_Sr[(b * L_ + lrow) * D_ + k0 + kc];
            sS[kc + 0][lrow] = v.x; sS[kc + 1][lrow] = v.y;
            sS[kc + 2][lrow] = v.z; sS[kc + 3][lrow] = v.w;
        }
#pragma unroll
        for (int i = 0; i < 2; i++) {
            int tt = lrow + i * 32;
            int t = t0 + tt;
            float4 w = make_float4(0.f, 0.f, 0.f, 0.f);
            if (t < T_) w = *(const float4*)&g_Vr[((long)b * T_ + t) * D_ + k0 + kc];
            sV[kc + 0][tt] = w.x; sV[kc + 1][tt] = w.y;
            sV[kc + 2][tt] = w.z; sV[kc + 3][tt] = w.w;
        }
        __syncthreads();
#pragma unroll
        for (int kk = 0; kk < 32; kk++) {
            float a0 = sS[kk][ty * 2], a1 = sS[kk][ty * 2 + 1];
            float4 bv = *(const float4*)&sV[kk][tx * 4];
            acc[0][0] += a0 * bv.x; acc[0][1] += a0 * bv.y;
            acc[0][2] += a0 * bv.z; acc[0][3] += a0 * bv.w;
            acc[1][0] += a1 * bv.x; acc[1][1] += a1 * bv.y;
            acc[1][2] += a1 * bv.z; acc[1][3] += a1 * bv.w;
        }
        __syncthreads();
    }
#pragma unroll
    for (int i = 0; i < 2; i++) {
        int l = ty * 2 + i;
#pragma unroll
        for (int j = 0; j < 4; j++) {
            int t = t0 + tx * 4 + j;
            if (t < T_) g_scores[(b * L_ + l) * T_ + t] = acc[i][j];
        }
    }
}

// ---------------- fused segprep + E aggregation (batch-offset) ----------------
// block (dc, g, b): computes m/Z/ws for segment g in-block (bit-identical order
// to the old segprep), then the E accumulation. Kills segprep launch + g_wtil.
__global__ void eagg_kernel(int bbase)
{
    int dc = blockIdx.x, g = blockIdx.y, b = bbase + blockIdx.z;
    int tid = threadIdx.x;
    int d = dc * 256 + tid;
    __shared__ float Vs[FPS_][256];
    __shared__ float sl[L_][FPS_ + 1];
    __shared__ float ws[L_][FPS_ + 1];
    __shared__ float sm[L_];

#pragma unroll
    for (int t = 0; t < FPS_; t++)
        Vs[t][tid] = g_Vr[((long)b * T_ + g * FPS_ + t) * D_ + d];
    for (int i = tid; i < L_ * FPS_; i += 256) {
        int l = i / FPS_, t = i % FPS_;
        sl[l][t] = g_scores[(b * L_ + l) * T_ + g * FPS_ + t];
    }
    __syncthreads();

    if (tid < L_) {
        int l = tid;
        float mx = -INFINITY;
#pragma unroll
        for (int i = 0; i < FPS_; i++) mx = fmaxf(mx, sl[l][i]);
        float z = 0.f;
#pragma unroll
        for (int i = 0; i < FPS_; i++) z += expf(sl[l][i] - mx);
        sm[l] = mx;
        if (dc == 0) {
            g_m[(b * L_ + l) * NSEG + g] = mx;
            g_Zs[(b * L_ + l) * NSEG + g] = z;
        }
    }
    __syncthreads();
    for (int i = tid; i < L_ * FPS_; i += 256) {
        int l = i / FPS_, t = i % FPS_;
        ws[l][t] = expf(sl[l][t] - sm[l]);
    }
    __syncthreads();

    for (int l = 0; l < L_; l++) {
        float acc = 0.f;
#pragma unroll
        for (int t = 0; t < FPS_; t++) acc += ws[l][t] * Vs[t][tid];
        g_E[((long)(b * L_ + l) * NSEG + g) * D_ + d] = acc;
    }
}

// ============================================================================
// prop_kernel v3: barrier-free chain streaming (batch-offset). UNchanged.
// ============================================================================
#define PCH 128
__global__ void __launch_bounds__(PCH) prop_kernel(const int* __restrict__ ytrue,
                                                   float* __restrict__ outPos, int bbase)
{
    int b = bbase + blockIdx.y, dc = blockIdx.x, sg = blockIdx.z;
    int tid = threadIdx.x;
    int d = dc * PCH + tid;

    __shared__ float s_m[L_][NSEG], s_Z[L_][NSEG];
    __shared__ float sSr[L_][PCH];
    __shared__ float c_sc[40][L_], c_an[40][L_], c_iz[40][L_];

    for (int i = tid; i < L_ * NSEG; i += PCH) {
        int l = i >> 4, g = i & 15;
        s_m[l][g] = g_m[(b * L_ + l) * NSEG + g];
        s_Z[l][g] = g_Zs[(b * L_ + l) * NSEG + g];
    }
    for (int i = tid; i < L_ * PCH; i += PCH) {
        int l = i / PCH, j = i % PCH;
        sSr[l][j] = g_Sr[(b * L_ + l) * D_ + dc * PCH + j];
    }
    __syncthreads();

    {
        int l = tid & 31, ci = tid >> 5;
        int s = sg + 4 * ci;
        int base = 0;
#pragma unroll
        for (int j = 0; j < 4; j++) if (j < ci) base += NSEG - (sg + 4 * j);
        float M = s_m[l][s], Zw = s_Z[l][s];
        c_sc[base][l] = 0.f; c_an[base][l] = 1.f; c_iz[base][l] = 1.f / Zw;
        for (int e = s + 1; e < NSEG; e++) {
            float mv = s_m[l][e];
            float Mn = fmaxf(M, mv);
            float sc = expf(M - Mn), an = expf(mv - Mn);
            Zw = Zw * sc + an * s_Z[l][e];
            M = Mn;
            int st = base + e - s;
            c_sc[st][l] = sc; c_an[st][l] = an; c_iz[st][l] = 1.f / Zw;
        }
    }
    __syncthreads();

    float sn = g_snorm[b * D_ + d];
    int ys = ytrue[2 * b], ye = ytrue[2 * b + 1];
    float negmax = -INFINITY;

    int base = 0;
#pragma unroll 1
    for (int ci = 0; ci < 4; ci++) {
        int s = sg + 4 * ci;
        float U[L_];
#pragma unroll
        for (int l = 0; l < L_; l++) U[l] = 0.f;
#pragma unroll 1
        for (int e = s; e < NSEG; e++) {
            int st = base + e - s;
            float num = 0.f, sq = 0.f;
            const float* Eb = g_E + ((long)(b * L_) * NSEG + e) * D_ + d;
#pragma unroll
            for (int l = 0; l < L_; l++) {
                float Ev = Eb[(long)l * NSEG * D_];
                float u = U[l] * c_sc[st][l] + c_an[st][l] * Ev;
                U[l] = u;
                float o = u * c_iz[st][l];
                num += o * sSr[l][tid];
                sq += o * o;
            }
            float scv = num / (sqrtf(sq) * sn + 1e-15f);
            if (s == ys && e == ye) outPos[b * D_ + d] = scv;
            else negmax = fmaxf(negmax, scv);
        }
        base += NSEG - s;
    }

#pragma unroll
    for (int off = 16; off; off >>= 1)
        negmax = fmaxf(negmax, __shfl_xor_sync(0xffffffffu, negmax, off));
    __shared__ float wm[4];
    if ((tid & 31) == 0) wm[tid >> 5] = negmax;
    __syncthreads();
    if (tid == 0) {
        float v = fmaxf(fmaxf(wm[0], wm[1]), fmaxf(wm[2], wm[3]));
        unsigned u = __float_as_uint(v);
        u = (u & 0x80000000u) ? ~u : (u | 0x80000000u);
        atomicMax(&g_negmax[b], u);
    }
}

__global__ void init_neg()
{
    if (threadIdx.x < B_) g_negmax[threadIdx.x] = 0x007FFFFFu;
}

__global__ void fin_kernel(float* __restrict__ outNeg)
{
    int b = threadIdx.x;
    if (b < B_) {
        unsigned u = g_negmax[b];
        unsigned bits = (u & 0x80000000u) ? (u ^ 0x80000000u) : ~u;
        outNeg[b] = __uint_as_float(bits);
    }
}

// ---------------- launch ----------------
extern "C" void kernel_launch(void* const* d_in, const int* in_sizes, int n_in,
                              void* d_out, int out_size)
{
    const float* videos    = (const float*)d_in[0];
    const float* sentences = (const float*)d_in[1];
    const float* Wv        = (const float*)d_in[2];
    const float* bv        = (const float*)d_in[3];
    const float* Ws        = (const float*)d_in[4];
    const float* bs        = (const float*)d_in[5];
    const int*   ytrue     = (const int*)d_in[6];
    float* out = (float*)d_out;

    float *pVr = nullptr, *pSr = nullptr;
    void *pBhi = nullptr, *pBlo = nullptr;
    cudaGetSymbolAddress((void**)&pVr, g_Vr);
    cudaGetSymbolAddress((void**)&pSr, g_Sr);
    cudaGetSymbolAddress(&pBhi, g_Bhi);
    cudaGetSymbolAddress(&pBlo, g_Blo);

    cudaFuncSetAttribute(vr_gemm, cudaFuncAttributeMaxDynamicSharedMemorySize, GEMM_SMEM);

    static cudaStream_t s2 = nullptr, s3 = nullptr;
    static cudaEvent_t evFork = nullptr, evSr = nullptr, evA = nullptr, evH1 = nullptr;
    if (s2 == nullptr) {
        cudaStreamCreateWithFlags(&s2, cudaStreamNonBlocking);
        cudaStreamCreateWithFlags(&s3, cudaStreamNonBlocking);
        cudaEventCreateWithFlags(&evFork, cudaEventDisableTiming);
        cudaEventCreateWithFlags(&evSr, cudaEventDisableTiming);
        cudaEventCreateWithFlags(&evA, cudaEventDisableTiming);
        cudaEventCreateWithFlags(&evH1, cudaEventDisableTiming);
    }

    init_neg<<<1, 32>>>();

    // fork: Sr path (sgemm64 -> snorm, exactly as R14) on s2
    cudaEventRecord(evFork, 0);
    cudaStreamWaitEvent(s2, evFork, 0);
    sgemm64_bias<<<dim3(D_ / 64, (B_ * L_) / 64), 256, 0, s2>>>(
        sentences, Ws, bs, pSr, B_ * L_, D_, DS_);
    snorm_kernel<<<(B_ * D_) / 256, 256, 0, s2>>>();
    cudaEventRecord(evSr, s2);

    // Vr path on the main stream: splitW, single full GEMM
    splitW_kernel<<<dim3(DV_ / 32, D_ / 32), dim3(32, 8)>>>(Wv,
        (__nv_bfloat16*)pBhi, (__nv_bfloat16*)pBlo);
    vr_gemm<<<dim3(D_ / 128, (B_ * T_) / 128), 256, GEMM_SMEM>>>(
        videos, (const __nv_bfloat16*)pBhi, (const __nv_bfloat16*)pBlo, bv, pVr);
    cudaEventRecord(evA, 0);

    // s3: batches 0..7 chain (scores -> fused eagg -> prop)
    cudaStreamWaitEvent(s3, evA, 0);
    cudaStreamWaitEvent(s3, evSr, 0);
    scores_kernel<<<dim3((T_ + 63) / 64, HALFB), 256, 0, s3>>>(0);
    eagg_kernel<<<dim3(D_ / 256, NSEG, HALFB), 256, 0, s3>>>(0);
    prop_kernel<<<dim3(D_ / PCH, HALFB, 4), PCH, 0, s3>>>(ytrue, out, 0);
    cudaEventRecord(evH1, s3);

    // main: batches 8..15 chain
    cudaStreamWaitEvent(0, evSr, 0);
    scores_kernel<<<dim3((T_ + 63) / 64, HALFB), 256>>>(HALFB);
    eagg_kernel<<<dim3(D_ / 256, NSEG, HALFB), 256>>>(HALFB);
    prop_kernel<<<dim3(D_ / PCH, HALFB, 4), PCH>>>(ytrue, out, HALFB);

    cudaStreamWaitEvent(0, evH1, 0);
    fin_kernel<<<1, 32>>>(out + B_ * D_);
}